// round 13
// baseline (speedup 1.0000x reference)
#include <cuda_runtime.h>
#include <cuda_bf16.h>
#include <math.h>
#include <stdint.h>

#define NN 2000
#define BB 64
#define EMBED 512
#define LABELS 20
#define NC 31            // Taylor degree 30

// ---- gemm0 (K1): MT=128 tile, 16 mtiles x 9 splits of 224 ----
#define SPLIT0 9
#define SPLEN0 224
#define G0_BLOCKS 144
#define A_PAD 72
#define K1_ALO 18432          // 128*144
#define K1_BHI 36864
#define K1_BLO 46080
#define K1_STRIDE 55296
#define DSMEM1 (2 * K1_STRIDE)   // 110592

// ---- gemm1 (K2 phase): MT=64 tile ----
#define TILEB 9216            // 64*144
#define K2_ALO TILEB
#define K2_BHI (2 * TILEB)
#define K2_BLO (3 * TILEB)
#define K2_STRIDE (4 * TILEB) // 36864
#define DSMEM2 (2 * K2_STRIDE)
#define SPLIT1 16
#define K2_BLOCKS 128

// ---- scratch ----
__device__ float g_mixed[BB * NN];           // [b][n]
__device__ float g_part1[SPLIT0 * NN * BB];  // [sp][n][b]
__device__ float g_part2[SPLIT1 * EMBED * BB];
__device__ float g_hT[EMBED * BB];           // [e][b]
__device__ float g_cn[NC][BB];
__device__ float g_cd[NC][BB];
__device__ float g_alpha, g_gamma;
__device__ unsigned g_ep2, g_ct2, g_ep3, g_ct3;   // monotonic barriers (no reset needed)

// grid barrier: epoch monotonic; all blocks must be co-resident
__device__ __forceinline__ void gsync(unsigned* ep, unsigned* ct, unsigned base,
                                      unsigned k, unsigned nblk) {
    __syncthreads();
    if (threadIdx.x == 0) {
        __threadfence();
        unsigned t = atomicAdd(ct, 1u);
        if (t == nblk - 1) {
            *ct = 0;
            __threadfence();
            atomicAdd(ep, 1u);
        } else {
            while (*(volatile unsigned*)ep - base < k) { __nanosleep(64); }
        }
        __threadfence();
    }
    __syncthreads();
}

__device__ __forceinline__ void mma16816(float* d, const uint32_t* a, const uint32_t* b) {
    asm volatile(
        "mma.sync.aligned.m16n8k16.row.col.f32.bf16.bf16.f32 "
        "{%0,%1,%2,%3}, {%4,%5,%6,%7}, {%8,%9}, {%0,%1,%2,%3};\n"
        : "+f"(d[0]), "+f"(d[1]), "+f"(d[2]), "+f"(d[3])
        : "r"(a[0]), "r"(a[1]), "r"(a[2]), "r"(a[3]), "r"(b[0]), "r"(b[1]));
}

__device__ __forceinline__ void split_store(char* hi, char* lo, int byte, float4 v) {
    __nv_bfloat16 hx = __float2bfloat16(v.x), hy = __float2bfloat16(v.y);
    __nv_bfloat16 hz = __float2bfloat16(v.z), hw = __float2bfloat16(v.w);
    float lx = v.x - __bfloat162float(hx), ly = v.y - __bfloat162float(hy);
    float lz = v.z - __bfloat162float(hz), lw = v.w - __bfloat162float(hw);
    uint2 h2, l2;
    h2.x = (unsigned)__bfloat16_as_ushort(hx) | ((unsigned)__bfloat16_as_ushort(hy) << 16);
    h2.y = (unsigned)__bfloat16_as_ushort(hz) | ((unsigned)__bfloat16_as_ushort(hw) << 16);
    __nv_bfloat16 ax = __float2bfloat16(lx), ay = __float2bfloat16(ly);
    __nv_bfloat16 az = __float2bfloat16(lz), aw = __float2bfloat16(lw);
    l2.x = (unsigned)__bfloat16_as_ushort(ax) | ((unsigned)__bfloat16_as_ushort(ay) << 16);
    l2.y = (unsigned)__bfloat16_as_ushort(az) | ((unsigned)__bfloat16_as_ushort(aw) << 16);
    *(uint2*)(hi + byte) = h2;
    *(uint2*)(lo + byte) = l2;
}

// ============================================================================
// K1: gemm0 — R5's verified 128x64-tile bf16-split mma kernel, 144 blocks,
//     one wave (1 CTA/SM at 110KB smem), no extra phases.
// ============================================================================
__global__ __launch_bounds__(256, 1)
void k_gemm0(const float* __restrict__ IG, const float* __restrict__ feat)
{
    extern __shared__ __align__(16) char dsm[];
    const int bid = blockIdx.x, tid = threadIdx.x;
    const int wid = tid >> 5, lane = tid & 31;
    const int mt = bid & 15, sp = bid >> 4;      // 16 mtiles x 9 splits
    const int rb = mt * 128;
    const int kb = sp * SPLEN0;
    int ke = kb + SPLEN0; if (ke > NN) ke = NN;
    const int nc = (ke - kb + 63) >> 6;

    const int warp_m = wid >> 1;                 // 0..3
    const int warp_n = wid & 1;                  // 0..1
    const int g = lane >> 2, tig = lane & 3;

    const int ar = tid >> 1, hh = tid & 1;       // A: row, k-half
    const int brr = tid >> 2, qq = tid & 3;      // B: b-row, k-quarter
    const bool rok = (rb + ar) < NN;
    const float* arow = IG + (size_t)(rb + ar) * NN;
    const float* brow = feat + (size_t)brr * NN;

    float acc[2][4][4];
#pragma unroll
    for (int t = 0; t < 2; t++)
#pragma unroll
        for (int u = 0; u < 4; u++)
#pragma unroll
            for (int j = 0; j < 4; j++) acc[t][u][j] = 0.f;

    float4 ra[8], rb4[4];
    auto ldg_chunk = [&](int c) {
        int m0 = kb + c * 64;
        int mlen = ke - m0; if (mlen > 64) mlen = 64;
#pragma unroll
        for (int i = 0; i < 8; i++) {
            int kk = hh * 32 + i * 4;
            float4 v = make_float4(0.f, 0.f, 0.f, 0.f);
            if (rok && kk + 4 <= mlen) v = *(const float4*)(arow + m0 + kk);
            ra[i] = v;
        }
#pragma unroll
        for (int i = 0; i < 4; i++) {
            int kk = qq * 16 + i * 4;
            float4 v = make_float4(0.f, 0.f, 0.f, 0.f);
            if (kk + 4 <= mlen) v = *(const float4*)(brow + m0 + kk);
            rb4[i] = v;
        }
    };
    auto cvt_store = [&](int p) {
        char* base = dsm + p * K1_STRIDE;
        char* Ahi = base;           char* Alo = base + K1_ALO;
        char* Bhi = base + K1_BHI;  char* Blo = base + K1_BLO;
#pragma unroll
        for (int i = 0; i < 8; i++) {
            int kk = hh * 32 + i * 4;
            split_store(Ahi, Alo, ar * (A_PAD * 2) + kk * 2, ra[i]);
        }
#pragma unroll
        for (int i = 0; i < 4; i++) {
            int kk = qq * 16 + i * 4;
            split_store(Bhi, Blo, brr * (A_PAD * 2) + kk * 2, rb4[i]);
        }
    };
    auto compute = [&](int p) {
        char* base = dsm + p * K1_STRIDE;
        char* Ahi = base;           char* Alo = base + K1_ALO;
        char* Bhi = base + K1_BHI;  char* Blo = base + K1_BLO;
#pragma unroll
        for (int ks = 0; ks < 4; ks++) {
            const int ko = ks * 16;
            uint32_t ah[2][4], al[2][4], bh[4][2], bl[4][2];
#pragma unroll
            for (int t = 0; t < 2; t++) {
                int row = warp_m * 32 + t * 16 + g;
                int o0 = row * (A_PAD * 2) + (ko + tig * 2) * 2;
                int o1 = (row + 8) * (A_PAD * 2) + (ko + tig * 2) * 2;
                ah[t][0] = *(uint32_t*)(Ahi + o0);
                ah[t][1] = *(uint32_t*)(Ahi + o1);
                ah[t][2] = *(uint32_t*)(Ahi + o0 + 16);
                ah[t][3] = *(uint32_t*)(Ahi + o1 + 16);
                al[t][0] = *(uint32_t*)(Alo + o0);
                al[t][1] = *(uint32_t*)(Alo + o1);
                al[t][2] = *(uint32_t*)(Alo + o0 + 16);
                al[t][3] = *(uint32_t*)(Alo + o1 + 16);
            }
#pragma unroll
            for (int u = 0; u < 4; u++) {
                int col = warp_n * 32 + u * 8 + g;
                int o = col * (A_PAD * 2) + (ko + tig * 2) * 2;
                bh[u][0] = *(uint32_t*)(Bhi + o);
                bh[u][1] = *(uint32_t*)(Bhi + o + 16);
                bl[u][0] = *(uint32_t*)(Blo + o);
                bl[u][1] = *(uint32_t*)(Blo + o + 16);
            }
#pragma unroll
            for (int t = 0; t < 2; t++)
#pragma unroll
                for (int u = 0; u < 4; u++) {
                    mma16816(acc[t][u], ah[t], bh[u]);
                    mma16816(acc[t][u], ah[t], bl[u]);
                    mma16816(acc[t][u], al[t], bh[u]);
                }
        }
    };

    ldg_chunk(0);
    for (int c = 0; c < nc; c++) {
        int p = c & 1;
        cvt_store(p);
        if (c + 1 < nc) ldg_chunk(c + 1);
        __syncthreads();
        compute(p);
    }

    float* dst = g_part1 + (size_t)sp * NN * BB;
#pragma unroll
    for (int t = 0; t < 2; t++) {
        int r0 = rb + warp_m * 32 + t * 16 + g;
#pragma unroll
        for (int u = 0; u < 4; u++) {
            int cn = warp_n * 32 + u * 8 + tig * 2;
            if (r0 < NN)
                *(float2*)(dst + (size_t)r0 * BB + cn) = make_float2(acc[t][u][0], acc[t][u][1]);
            if (r0 + 8 < NN)
                *(float2*)(dst + (size_t)(r0 + 8) * BB + cn) = make_float2(acc[t][u][2], acc[t][u][3]);
        }
    }
}

// MT=64 gemm tile for fc1 (R10-verified scalar-LDS version)
__device__ __forceinline__ void gemm_tile64(
    const float* __restrict__ A, const float* __restrict__ Bmat,
    float* __restrict__ dst, int nrows, int rb, int kb, int ke,
    char* dsm, int tid)
{
    const int wid = tid >> 5, lane = tid & 31;
    const int warp_m = wid >> 2, warp_n = wid & 3;
    const int g = lane >> 2, tig = lane & 3;
    const int rr = tid >> 2;
    const int q4 = (tid & 3) * 16;
    const bool rok = (rb + rr) < nrows;
    const float* arow = A + (size_t)(rb + rr) * NN;
    const float* brow = Bmat + (size_t)rr * NN;
    const int nc = (ke - kb + 63) >> 6;

    float acc[2][2][4];
#pragma unroll
    for (int t = 0; t < 2; t++)
#pragma unroll
        for (int u = 0; u < 2; u++)
#pragma unroll
            for (int j = 0; j < 4; j++) acc[t][u][j] = 0.f;

    float4 ra[4], rbv[4];
    auto ldg_chunk = [&](int c) {
        int m0 = kb + c * 64;
        int mlen = ke - m0; if (mlen > 64) mlen = 64;
#pragma unroll
        for (int i = 0; i < 4; i++) {
            int kk = q4 + i * 4;
            bool ok = (kk + 4 <= mlen);
            ra[i] = (rok && ok) ? *(const float4*)(arow + m0 + kk)
                                : make_float4(0.f, 0.f, 0.f, 0.f);
            rbv[i] = ok ? *(const float4*)(brow + m0 + kk)
                        : make_float4(0.f, 0.f, 0.f, 0.f);
        }
    };
    auto cvt_store = [&](int p) {
        char* base = dsm + p * K2_STRIDE;
#pragma unroll
        for (int i = 0; i < 4; i++) {
            int kk = q4 + i * 4;
            split_store(base, base + K2_ALO, rr * (A_PAD * 2) + kk * 2, ra[i]);
            split_store(base + K2_BHI, base + K2_BLO, rr * (A_PAD * 2) + kk * 2, rbv[i]);
        }
    };
    auto compute = [&](int p) {
        char* base = dsm + p * K2_STRIDE;
        char* Ahi = base;           char* Alo = base + K2_ALO;
        char* Bhi = base + K2_BHI;  char* Blo = base + K2_BLO;
#pragma unroll
        for (int ks = 0; ks < 4; ks++) {
            const int ko = ks * 16;
            uint32_t ah[2][4], al[2][4], bh[2][2], bl[2][2];
#pragma unroll
            for (int t = 0; t < 2; t++) {
                int row = warp_m * 32 + t * 16 + g;
                int o0 = row * (A_PAD * 2) + (ko + tig * 2) * 2;
                int o1 = (row + 8) * (A_PAD * 2) + (ko + tig * 2) * 2;
                ah[t][0] = *(uint32_t*)(Ahi + o0);
                ah[t][1] = *(uint32_t*)(Ahi + o1);
                ah[t][2] = *(uint32_t*)(Ahi + o0 + 16);
                ah[t][3] = *(uint32_t*)(Ahi + o1 + 16);
                al[t][0] = *(uint32_t*)(Alo + o0);
                al[t][1] = *(uint32_t*)(Alo + o1);
                al[t][2] = *(uint32_t*)(Alo + o0 + 16);
                al[t][3] = *(uint32_t*)(Alo + o1 + 16);
            }
#pragma unroll
            for (int u = 0; u < 2; u++) {
                int col = warp_n * 16 + u * 8 + g;
                int o = col * (A_PAD * 2) + (ko + tig * 2) * 2;
                bh[u][0] = *(uint32_t*)(Bhi + o);
                bh[u][1] = *(uint32_t*)(Bhi + o + 16);
                bl[u][0] = *(uint32_t*)(Blo + o);
                bl[u][1] = *(uint32_t*)(Blo + o + 16);
            }
#pragma unroll
            for (int t = 0; t < 2; t++)
#pragma unroll
                for (int u = 0; u < 2; u++) {
                    mma16816(acc[t][u], ah[t], bh[u]);
                    mma16816(acc[t][u], ah[t], bl[u]);
                    mma16816(acc[t][u], al[t], bh[u]);
                }
        }
    };

    ldg_chunk(0);
    for (int c = 0; c < nc; c++) {
        int p = c & 1;
        cvt_store(p);
        if (c + 1 < nc) ldg_chunk(c + 1);
        __syncthreads();
        compute(p);
    }

#pragma unroll
    for (int t = 0; t < 2; t++) {
        int r0 = rb + warp_m * 32 + t * 16 + g;
#pragma unroll
        for (int u = 0; u < 2; u++) {
            int cn = warp_n * 16 + u * 8 + tig * 2;
            if (r0 < nrows)
                *(float2*)(dst + (size_t)r0 * BB + cn) = make_float2(acc[t][u][0], acc[t][u][1]);
            if (r0 + 8 < nrows)
                *(float2*)(dst + (size_t)(r0 + 8) * BB + cn) = make_float2(acc[t][u][2], acc[t][u][3]);
        }
    }
}

// ============================================================================
// K2: moments -> barrier -> mix -> barrier -> fc1 gemm. 128 blocks (co-resident).
// ============================================================================
__global__ __launch_bounds__(256, 1)
void k_mid(const float* __restrict__ feat, const float* __restrict__ tw,
           const float* __restrict__ tb, const float* __restrict__ pw,
           const float* __restrict__ w1)
{
    extern __shared__ __align__(16) char dsm[];
    const int bid = blockIdx.x, tid = threadIdx.x;
    unsigned base = 0;
    if (tid == 0) base = *(volatile unsigned*)&g_ep2;

    // ---------------- phase 0: moments (blocks 0..63, one batch each) -------
    if (bid < 64) {
        if (bid == 0) {
            __shared__ float sa[64], sg[64];
            if (tid < 64) { sa[tid] = tw[tid] * pw[tid]; sg[tid] = tb[tid] * pw[tid]; }
            __syncthreads();
            if (tid == 0) {
                float A = 0.f, G = 0.f;
                for (int i = 0; i < 64; i++) { A += sa[i]; G += sg[i]; }
                g_alpha = A; g_gamma = G;
            }
            __syncthreads();
        }
        const int b = bid;
        const float* xr = feat + (size_t)b * NN;
        float acc[32];
#pragma unroll
        for (int k = 0; k < 32; k++) acc[k] = 0.f;
        for (int m = tid; m < NN; m += 256) {
            float v = xr[m];
            float p = 1.f;
#pragma unroll
            for (int k = 0; k < 32; k++) { acc[k] += p; p *= v; }
        }
#pragma unroll
        for (int k = 0; k < 32; k++) {
#pragma unroll
            for (int off = 16; off > 0; off >>= 1)
                acc[k] += __shfl_down_sync(0xffffffffu, acc[k], off);
        }
        __shared__ float red[32][8];
        __shared__ float sM[32];
        int lane = tid & 31, warp = tid >> 5;
        if (lane == 0) {
#pragma unroll
            for (int k = 0; k < 32; k++) red[k][warp] = acc[k];
        }
        __syncthreads();
        if (tid < 32) {
            float s = 0.f;
            for (int w = 0; w < 8; w++) s += red[tid][w];
            sM[tid] = s;
        }
        __syncthreads();
        if (tid < NC) {
            int k = tid;
            float fact = 1.f;
            for (int i = 2; i <= k; i++) fact *= (float)i;
            g_cd[k][b] = sM[k] / fact;
            g_cn[k][b] = sM[k + 1] / fact;
        }
    }
    gsync(&g_ep2, &g_ct2, base, 1, K2_BLOCKS);

    // ---------------- phase 1: mix (blocks 0..124, one 16-n chunk each) -----
    if (bid < 125) {
        __shared__ float xs[64][17];
        __shared__ float ms[16][68];
        const int n0 = bid * 16;
        {
            int bl = tid >> 2, no = (tid & 3) * 4;
            float4 v = *(const float4*)(feat + (size_t)bl * NN + n0 + no);
            xs[bl][no] = v.x; xs[bl][no + 1] = v.y;
            xs[bl][no + 2] = v.z; xs[bl][no + 3] = v.w;
        }
        __syncthreads();
        {
            int nl = tid >> 4, b4 = (tid & 15) * 4;
            size_t row = (size_t)(n0 + nl) * BB + b4;
            float4 pre = *(float4*)(g_part1 + row);
#pragma unroll
            for (int p = 1; p < SPLIT0; p++) {
                float4 v = *(float4*)(g_part1 + (size_t)p * NN * BB + row);
                pre.x += v.x; pre.y += v.y; pre.z += v.z; pre.w += v.w;
            }
            float al = g_alpha, ga = g_gamma;
            float xv0 = xs[b4 + 0][nl], xv1 = xs[b4 + 1][nl];
            float xv2 = xs[b4 + 2][nl], xv3 = xs[b4 + 3][nl];
            float s0 = al * xv0 + ga, s1 = al * xv1 + ga;
            float s2 = al * xv2 + ga, s3 = al * xv3 + ga;
            float4 P = *(float4*)&g_cn[NC - 1][b4];
            float4 Q = *(float4*)&g_cd[NC - 1][b4];
#pragma unroll
            for (int k = NC - 2; k >= 0; k--) {
                float4 cn = *(float4*)&g_cn[k][b4];
                float4 cd = *(float4*)&g_cd[k][b4];
                P.x = P.x * s0 + cn.x; Q.x = Q.x * s0 + cd.x;
                P.y = P.y * s1 + cn.y; Q.y = Q.y * s1 + cd.y;
                P.z = P.z * s2 + cn.z; Q.z = Q.z * s2 + cd.z;
                P.w = P.w * s3 + cn.w; Q.w = Q.w * s3 + cd.w;
            }
            float r0 = pre.x + P.x / Q.x, r1 = pre.y + P.y / Q.y;
            float r2 = pre.z + P.z / Q.z, r3 = pre.w + P.w / Q.w;
            ms[nl][b4 + 0] = (r0 > 0.f ? r0 : 0.f) + xv0;
            ms[nl][b4 + 1] = (r1 > 0.f ? r1 : 0.f) + xv1;
            ms[nl][b4 + 2] = (r2 > 0.f ? r2 : 0.f) + xv2;
            ms[nl][b4 + 3] = (r3 > 0.f ? r3 : 0.f) + xv3;
        }
        __syncthreads();
        {
            int bl = tid >> 2, no = (tid & 3) * 4;
            float4 v = make_float4(ms[no][bl], ms[no + 1][bl], ms[no + 2][bl], ms[no + 3][bl]);
            *(float4*)(g_mixed + (size_t)bl * NN + n0 + no) = v;
        }
    }
    gsync(&g_ep2, &g_ct2, base, 2, K2_BLOCKS);

    // ---------------- phase 2: fc1 gemm (8 mtiles x 16 splits) --------------
    {
        int mt = bid & 7, sp = bid >> 3;
        int kb = sp * 128, ke = kb + 128; if (ke > NN) ke = NN;
        gemm_tile64(w1, g_mixed, g_part2 + (size_t)sp * EMBED * BB, EMBED,
                    mt * 64, kb, ke, dsm, tid);
    }
}

// ============================================================================
// K3: hid (reduce 16 partials + bias + fast tanh) -> barrier -> logits.
//     20 blocks (co-resident).
// ============================================================================
__global__ __launch_bounds__(256)
void k_tail(const float* __restrict__ b1, const float* __restrict__ w2,
            const float* __restrict__ b2, float* __restrict__ out)
{
    const int bid = blockIdx.x, tid = threadIdx.x;
    unsigned base = 0;
    if (tid == 0) base = *(volatile unsigned*)&g_ep3;

    // hid: EMBED*BB/4 = 8192 float4 spread over 20*256 threads
    for (int i = bid * 256 + tid; i < EMBED * BB / 4; i += LABELS * 256) {
        int idx4 = i * 4;
        int e = idx4 >> 6;
        float bb1 = b1[e];
        float4 s = make_float4(bb1, bb1, bb1, bb1);
#pragma unroll
        for (int p = 0; p < SPLIT1; p++) {
            float4 v = *(float4*)(g_part2 + (size_t)p * EMBED * BB + idx4);
            s.x += v.x; s.y += v.y; s.z += v.z; s.w += v.w;
        }
        float4 h;
        h.x = 1.f - __fdividef(2.f, __expf(2.f * s.x) + 1.f);
        h.y = 1.f - __fdividef(2.f, __expf(2.f * s.y) + 1.f);
        h.z = 1.f - __fdividef(2.f, __expf(2.f * s.z) + 1.f);
        h.w = 1.f - __fdividef(2.f, __expf(2.f * s.w) + 1.f);
        *(float4*)(g_hT + idx4) = h;
    }
    gsync(&g_ep3, &g_ct3, base, 1, LABELS);

    // logits
    int l = bid;
    int b = tid & 63, qq = tid >> 6;
    const float* wr = w2 + l * EMBED + qq * 128;
    const float* hp = g_hT + (qq * 128) * BB + b;
    float acc = 0.f;
#pragma unroll 8
    for (int e = 0; e < 128; e++) acc += wr[e] * hp[e * BB];
    __shared__ float s[256];
    s[tid] = acc;
    __syncthreads();
    if (qq == 0)
        out[b * LABELS + l] = s[b] + s[64 + b] + s[128 + b] + s[192 + b] + b2[l];
}

extern "C" void kernel_launch(void* const* d_in, const int* in_sizes, int n_in,
                              void* d_out, int out_size) {
    const float* feature    = (const float*)d_in[0];
    const float* init_graph = (const float*)d_in[1];
    const float* theta_w    = (const float*)d_in[2];
    const float* theta_b    = (const float*)d_in[3];
    const float* phi_w      = (const float*)d_in[4];
    /* phi_b cancels in the softmax */
    const float* fc1_w      = (const float*)d_in[6];
    const float* fc1_b      = (const float*)d_in[7];
    const float* fc2_w      = (const float*)d_in[8];
    const float* fc2_b      = (const float*)d_in[9];
    float* out = (float*)d_out;

    cudaFuncSetAttribute(k_gemm0, cudaFuncAttributeMaxDynamicSharedMemorySize, DSMEM1);
    cudaFuncSetAttribute(k_mid, cudaFuncAttributeMaxDynamicSharedMemorySize, DSMEM2);

    k_gemm0<<<G0_BLOCKS, 256, DSMEM1>>>(init_graph, feature);
    k_mid<<<K2_BLOCKS, 256, DSMEM2>>>(feature, theta_w, theta_b, phi_w, fc1_w);
    k_tail<<<LABELS, 256>>>(fc1_b, fc2_w, fc2_b, out);
}

// round 14
// speedup vs baseline: 1.1138x; 1.1138x over previous
#include <cuda_runtime.h>
#include <cuda_bf16.h>
#include <math.h>
#include <stdint.h>

#define NN 2000
#define BB 64
#define EMBED 512
#define LABELS 20
#define NC 31            // Taylor degree 30

// ---- gemm0 (K1): MT=128 tile, 16 mtiles x 9 splits of 224, 512 threads ----
#define SPLIT0 9
#define SPLEN0 224
#define G0_BLOCKS 144
#define A_PAD 72
#define K1_ALO 18432
#define K1_BHI 36864
#define K1_BLO 46080
#define K1_STRIDE 55296
#define DSMEM1 (2 * K1_STRIDE)   // 110592

// ---- gemm1 (K2 phase): MT=64 tile, 256 threads ----
#define TILEB 9216
#define K2_ALO TILEB
#define K2_BHI (2 * TILEB)
#define K2_BLO (3 * TILEB)
#define K2_STRIDE (4 * TILEB)
#define DSMEM2 (2 * K2_STRIDE)   // 73728
#define SPLIT1 16
#define K2_BLOCKS 128
#define K3_BLOCKS 128

// ---- scratch ----
__device__ float g_mixed[BB * NN];           // [b][n]
__device__ float g_part1[SPLIT0 * NN * BB];  // [sp][n][b]
__device__ float g_part2[SPLIT1 * EMBED * BB];
__device__ float g_hT[EMBED * BB];           // [e][b]
__device__ float g_cn[NC][BB];
__device__ float g_cd[NC][BB];
__device__ float g_alpha, g_gamma;
__device__ unsigned g_ep2, g_ct2, g_ep3, g_ct3;   // monotonic barriers

__device__ __forceinline__ void gsync(unsigned* ep, unsigned* ct, unsigned base,
                                      unsigned k, unsigned nblk) {
    __syncthreads();
    if (threadIdx.x == 0) {
        __threadfence();
        unsigned t = atomicAdd(ct, 1u);
        if (t == nblk - 1) {
            *ct = 0;
            __threadfence();
            atomicAdd(ep, 1u);
        } else {
            while (*(volatile unsigned*)ep - base < k) { __nanosleep(64); }
        }
        __threadfence();
    }
    __syncthreads();
}

__device__ __forceinline__ void mma16816(float* d, const uint32_t* a, const uint32_t* b) {
    asm volatile(
        "mma.sync.aligned.m16n8k16.row.col.f32.bf16.bf16.f32 "
        "{%0,%1,%2,%3}, {%4,%5,%6,%7}, {%8,%9}, {%0,%1,%2,%3};\n"
        : "+f"(d[0]), "+f"(d[1]), "+f"(d[2]), "+f"(d[3])
        : "r"(a[0]), "r"(a[1]), "r"(a[2]), "r"(a[3]), "r"(b[0]), "r"(b[1]));
}

__device__ __forceinline__ void split_store(char* hi, char* lo, int byte, float4 v) {
    __nv_bfloat16 hx = __float2bfloat16(v.x), hy = __float2bfloat16(v.y);
    __nv_bfloat16 hz = __float2bfloat16(v.z), hw = __float2bfloat16(v.w);
    float lx = v.x - __bfloat162float(hx), ly = v.y - __bfloat162float(hy);
    float lz = v.z - __bfloat162float(hz), lw = v.w - __bfloat162float(hw);
    uint2 h2, l2;
    h2.x = (unsigned)__bfloat16_as_ushort(hx) | ((unsigned)__bfloat16_as_ushort(hy) << 16);
    h2.y = (unsigned)__bfloat16_as_ushort(hz) | ((unsigned)__bfloat16_as_ushort(hw) << 16);
    __nv_bfloat16 ax = __float2bfloat16(lx), ay = __float2bfloat16(ly);
    __nv_bfloat16 az = __float2bfloat16(lz), aw = __float2bfloat16(lw);
    l2.x = (unsigned)__bfloat16_as_ushort(ax) | ((unsigned)__bfloat16_as_ushort(ay) << 16);
    l2.y = (unsigned)__bfloat16_as_ushort(az) | ((unsigned)__bfloat16_as_ushort(aw) << 16);
    *(uint2*)(hi + byte) = h2;
    *(uint2*)(lo + byte) = l2;
}

// ============================================================================
// K1: gemm0 at 512 threads (16 warps, 4x4 warp grid over 128x64 tile)
//     + moments blocks 144..207
// ============================================================================
__global__ __launch_bounds__(512, 1)
void k_gemm0(const float* __restrict__ IG, const float* __restrict__ feat,
             const float* __restrict__ tw, const float* __restrict__ tb,
             const float* __restrict__ pw)
{
    extern __shared__ __align__(16) char dsm[];
    const int bid = blockIdx.x, tid = threadIdx.x;

    if (bid >= G0_BLOCKS) {
        // ----------------- moments: one batch per block ---------------------
        if (bid == G0_BLOCKS) {
            __shared__ float sa[64], sg[64];
            if (tid < 64) { sa[tid] = tw[tid] * pw[tid]; sg[tid] = tb[tid] * pw[tid]; }
            __syncthreads();
            if (tid == 0) {
                float A = 0.f, G = 0.f;
                for (int i = 0; i < 64; i++) { A += sa[i]; G += sg[i]; }
                g_alpha = A; g_gamma = G;
            }
            __syncthreads();
        }
        const int b = bid - G0_BLOCKS;
        const float* xr = feat + (size_t)b * NN;
        float acc[32];
#pragma unroll
        for (int k = 0; k < 32; k++) acc[k] = 0.f;
        for (int m = tid; m < NN; m += 512) {
            float v = xr[m];
            float p = 1.f;
#pragma unroll
            for (int k = 0; k < 32; k++) { acc[k] += p; p *= v; }
        }
#pragma unroll
        for (int k = 0; k < 32; k++) {
#pragma unroll
            for (int off = 16; off > 0; off >>= 1)
                acc[k] += __shfl_down_sync(0xffffffffu, acc[k], off);
        }
        __shared__ float red[32][16];
        __shared__ float sM[32];
        int lane = tid & 31, warp = tid >> 5;
        if (lane == 0) {
#pragma unroll
            for (int k = 0; k < 32; k++) red[k][warp] = acc[k];
        }
        __syncthreads();
        if (tid < 32) {
            float s = 0.f;
            for (int w = 0; w < 16; w++) s += red[tid][w];
            sM[tid] = s;
        }
        __syncthreads();
        if (tid < NC) {
            int k = tid;
            float fact = 1.f;
            for (int i = 2; i <= k; i++) fact *= (float)i;
            g_cd[k][b] = sM[k] / fact;
            g_cn[k][b] = sM[k + 1] / fact;
        }
        return;
    }

    // ----------------- gemm0 tile --------------------------------------------
    const int wid = tid >> 5, lane = tid & 31;
    const int mt = bid & 15, sp = bid >> 4;
    const int rb = mt * 128;
    const int kb = sp * SPLEN0;
    int ke = kb + SPLEN0; if (ke > NN) ke = NN;
    const int nc = (ke - kb + 63) >> 6;

    const int warp_m = wid >> 2;          // 0..3 -> rows *32
    const int warp_n = wid & 3;           // 0..3 -> cols *16
    const int g = lane >> 2, tig = lane & 3;

    const int ar = tid >> 2;              // A row 0..127
    const int aq = (tid & 3) * 16;        // A k quarter
    const int brr = tid >> 3;             // B row 0..63
    const int bq = (tid & 7) * 8;         // B k eighth
    const bool rok = (rb + ar) < NN;
    const float* arow = IG + (size_t)(rb + ar) * NN;
    const float* brow = feat + (size_t)brr * NN;

    float acc[2][2][4];
#pragma unroll
    for (int t = 0; t < 2; t++)
#pragma unroll
        for (int u = 0; u < 2; u++)
#pragma unroll
            for (int j = 0; j < 4; j++) acc[t][u][j] = 0.f;

    float4 ra[4], rbv[2];
    auto ldg_chunk = [&](int c) {
        int m0 = kb + c * 64;
        int mlen = ke - m0; if (mlen > 64) mlen = 64;
#pragma unroll
        for (int i = 0; i < 4; i++) {
            int kk = aq + i * 4;
            float4 v = make_float4(0.f, 0.f, 0.f, 0.f);
            if (rok && kk + 4 <= mlen) v = *(const float4*)(arow + m0 + kk);
            ra[i] = v;
        }
#pragma unroll
        for (int i = 0; i < 2; i++) {
            int kk = bq + i * 4;
            float4 v = make_float4(0.f, 0.f, 0.f, 0.f);
            if (kk + 4 <= mlen) v = *(const float4*)(brow + m0 + kk);
            rbv[i] = v;
        }
    };
    auto cvt_store = [&](int p) {
        char* base = dsm + p * K1_STRIDE;
#pragma unroll
        for (int i = 0; i < 4; i++) {
            int kk = aq + i * 4;
            split_store(base, base + K1_ALO, ar * (A_PAD * 2) + kk * 2, ra[i]);
        }
#pragma unroll
        for (int i = 0; i < 2; i++) {
            int kk = bq + i * 4;
            split_store(base + K1_BHI, base + K1_BLO, brr * (A_PAD * 2) + kk * 2, rbv[i]);
        }
    };
    auto compute = [&](int p) {
        char* base = dsm + p * K1_STRIDE;
        char* Ahi = base;           char* Alo = base + K1_ALO;
        char* Bhi = base + K1_BHI;  char* Blo = base + K1_BLO;
#pragma unroll
        for (int ks = 0; ks < 4; ks++) {
            const int ko = ks * 16;
            uint32_t ah[2][4], al[2][4], bh[2][2], bl[2][2];
#pragma unroll
            for (int t = 0; t < 2; t++) {
                int row = warp_m * 32 + t * 16 + g;
                int o0 = row * (A_PAD * 2) + (ko + tig * 2) * 2;
                int o1 = (row + 8) * (A_PAD * 2) + (ko + tig * 2) * 2;
                ah[t][0] = *(uint32_t*)(Ahi + o0);
                ah[t][1] = *(uint32_t*)(Ahi + o1);
                ah[t][2] = *(uint32_t*)(Ahi + o0 + 16);
                ah[t][3] = *(uint32_t*)(Ahi + o1 + 16);
                al[t][0] = *(uint32_t*)(Alo + o0);
                al[t][1] = *(uint32_t*)(Alo + o1);
                al[t][2] = *(uint32_t*)(Alo + o0 + 16);
                al[t][3] = *(uint32_t*)(Alo + o1 + 16);
            }
#pragma unroll
            for (int u = 0; u < 2; u++) {
                int col = warp_n * 16 + u * 8 + g;
                int o = col * (A_PAD * 2) + (ko + tig * 2) * 2;
                bh[u][0] = *(uint32_t*)(Bhi + o);
                bh[u][1] = *(uint32_t*)(Bhi + o + 16);
                bl[u][0] = *(uint32_t*)(Blo + o);
                bl[u][1] = *(uint32_t*)(Blo + o + 16);
            }
#pragma unroll
            for (int t = 0; t < 2; t++)
#pragma unroll
                for (int u = 0; u < 2; u++) {
                    mma16816(acc[t][u], ah[t], bh[u]);
                    mma16816(acc[t][u], ah[t], bl[u]);
                    mma16816(acc[t][u], al[t], bh[u]);
                }
        }
    };

    ldg_chunk(0);
    for (int c = 0; c < nc; c++) {
        int p = c & 1;
        cvt_store(p);
        if (c + 1 < nc) ldg_chunk(c + 1);
        __syncthreads();
        compute(p);
    }

    float* dst = g_part1 + (size_t)sp * NN * BB;
#pragma unroll
    for (int t = 0; t < 2; t++) {
        int r0 = rb + warp_m * 32 + t * 16 + g;
#pragma unroll
        for (int u = 0; u < 2; u++) {
            int cn = warp_n * 16 + u * 8 + tig * 2;
            if (r0 < NN)
                *(float2*)(dst + (size_t)r0 * BB + cn) = make_float2(acc[t][u][0], acc[t][u][1]);
            if (r0 + 8 < NN)
                *(float2*)(dst + (size_t)(r0 + 8) * BB + cn) = make_float2(acc[t][u][2], acc[t][u][3]);
        }
    }
}

// MT=64 gemm tile for fc1 (R10-verified, 256 threads)
__device__ __forceinline__ void gemm_tile64(
    const float* __restrict__ A, const float* __restrict__ Bmat,
    float* __restrict__ dst, int nrows, int rb, int kb, int ke,
    char* dsm, int tid)
{
    const int wid = tid >> 5, lane = tid & 31;
    const int warp_m = wid >> 2, warp_n = wid & 3;
    const int g = lane >> 2, tig = lane & 3;
    const int rr = tid >> 2;
    const int q4 = (tid & 3) * 16;
    const bool rok = (rb + rr) < nrows;
    const float* arow = A + (size_t)(rb + rr) * NN;
    const float* brow = Bmat + (size_t)rr * NN;
    const int nc = (ke - kb + 63) >> 6;

    float acc[2][2][4];
#pragma unroll
    for (int t = 0; t < 2; t++)
#pragma unroll
        for (int u = 0; u < 2; u++)
#pragma unroll
            for (int j = 0; j < 4; j++) acc[t][u][j] = 0.f;

    float4 ra[4], rbv[4];
    auto ldg_chunk = [&](int c) {
        int m0 = kb + c * 64;
        int mlen = ke - m0; if (mlen > 64) mlen = 64;
#pragma unroll
        for (int i = 0; i < 4; i++) {
            int kk = q4 + i * 4;
            bool ok = (kk + 4 <= mlen);
            ra[i] = (rok && ok) ? *(const float4*)(arow + m0 + kk)
                                : make_float4(0.f, 0.f, 0.f, 0.f);
            rbv[i] = ok ? *(const float4*)(brow + m0 + kk)
                        : make_float4(0.f, 0.f, 0.f, 0.f);
        }
    };
    auto cvt_store = [&](int p) {
        char* base = dsm + p * K2_STRIDE;
#pragma unroll
        for (int i = 0; i < 4; i++) {
            int kk = q4 + i * 4;
            split_store(base, base + K2_ALO, rr * (A_PAD * 2) + kk * 2, ra[i]);
            split_store(base + K2_BHI, base + K2_BLO, rr * (A_PAD * 2) + kk * 2, rbv[i]);
        }
    };
    auto compute = [&](int p) {
        char* base = dsm + p * K2_STRIDE;
        char* Ahi = base;           char* Alo = base + K2_ALO;
        char* Bhi = base + K2_BHI;  char* Blo = base + K2_BLO;
#pragma unroll
        for (int ks = 0; ks < 4; ks++) {
            const int ko = ks * 16;
            uint32_t ah[2][4], al[2][4], bh[2][2], bl[2][2];
#pragma unroll
            for (int t = 0; t < 2; t++) {
                int row = warp_m * 32 + t * 16 + g;
                int o0 = row * (A_PAD * 2) + (ko + tig * 2) * 2;
                int o1 = (row + 8) * (A_PAD * 2) + (ko + tig * 2) * 2;
                ah[t][0] = *(uint32_t*)(Ahi + o0);
                ah[t][1] = *(uint32_t*)(Ahi + o1);
                ah[t][2] = *(uint32_t*)(Ahi + o0 + 16);
                ah[t][3] = *(uint32_t*)(Ahi + o1 + 16);
                al[t][0] = *(uint32_t*)(Alo + o0);
                al[t][1] = *(uint32_t*)(Alo + o1);
                al[t][2] = *(uint32_t*)(Alo + o0 + 16);
                al[t][3] = *(uint32_t*)(Alo + o1 + 16);
            }
#pragma unroll
            for (int u = 0; u < 2; u++) {
                int col = warp_n * 16 + u * 8 + g;
                int o = col * (A_PAD * 2) + (ko + tig * 2) * 2;
                bh[u][0] = *(uint32_t*)(Bhi + o);
                bh[u][1] = *(uint32_t*)(Bhi + o + 16);
                bl[u][0] = *(uint32_t*)(Blo + o);
                bl[u][1] = *(uint32_t*)(Blo + o + 16);
            }
#pragma unroll
            for (int t = 0; t < 2; t++)
#pragma unroll
                for (int u = 0; u < 2; u++) {
                    mma16816(acc[t][u], ah[t], bh[u]);
                    mma16816(acc[t][u], ah[t], bl[u]);
                    mma16816(acc[t][u], al[t], bh[u]);
                }
        }
    };

    ldg_chunk(0);
    for (int c = 0; c < nc; c++) {
        int p = c & 1;
        cvt_store(p);
        if (c + 1 < nc) ldg_chunk(c + 1);
        __syncthreads();
        compute(p);
    }

#pragma unroll
    for (int t = 0; t < 2; t++) {
        int r0 = rb + warp_m * 32 + t * 16 + g;
#pragma unroll
        for (int u = 0; u < 2; u++) {
            int cn = warp_n * 16 + u * 8 + tig * 2;
            if (r0 < nrows)
                *(float2*)(dst + (size_t)r0 * BB + cn) = make_float2(acc[t][u][0], acc[t][u][1]);
            if (r0 + 8 < nrows)
                *(float2*)(dst + (size_t)(r0 + 8) * BB + cn) = make_float2(acc[t][u][2], acc[t][u][3]);
        }
    }
}

// ============================================================================
// K2: mix (125 of 128 blocks) -> barrier -> fc1 gemm (128 blocks).
// ============================================================================
__global__ __launch_bounds__(256, 1)
void k_mid(const float* __restrict__ feat, const float* __restrict__ w1)
{
    extern __shared__ __align__(16) char dsm[];
    const int bid = blockIdx.x, tid = threadIdx.x;
    unsigned base = 0;
    if (tid == 0) base = *(volatile unsigned*)&g_ep2;

    if (bid < 125) {
        __shared__ float xs[64][17];
        __shared__ float ms[16][68];
        const int n0 = bid * 16;
        {
            int bl = tid >> 2, no = (tid & 3) * 4;
            float4 v = *(const float4*)(feat + (size_t)bl * NN + n0 + no);
            xs[bl][no] = v.x; xs[bl][no + 1] = v.y;
            xs[bl][no + 2] = v.z; xs[bl][no + 3] = v.w;
        }
        __syncthreads();
        {
            int nl = tid >> 4, b4 = (tid & 15) * 4;
            size_t row = (size_t)(n0 + nl) * BB + b4;
            float4 pre = *(float4*)(g_part1 + row);
#pragma unroll
            for (int p = 1; p < SPLIT0; p++) {
                float4 v = *(float4*)(g_part1 + (size_t)p * NN * BB + row);
                pre.x += v.x; pre.y += v.y; pre.z += v.z; pre.w += v.w;
            }
            float al = g_alpha, ga = g_gamma;
            float xv0 = xs[b4 + 0][nl], xv1 = xs[b4 + 1][nl];
            float xv2 = xs[b4 + 2][nl], xv3 = xs[b4 + 3][nl];
            float s0 = al * xv0 + ga, s1 = al * xv1 + ga;
            float s2 = al * xv2 + ga, s3 = al * xv3 + ga;
            float4 P = *(float4*)&g_cn[NC - 1][b4];
            float4 Q = *(float4*)&g_cd[NC - 1][b4];
#pragma unroll
            for (int k = NC - 2; k >= 0; k--) {
                float4 cn = *(float4*)&g_cn[k][b4];
                float4 cd = *(float4*)&g_cd[k][b4];
                P.x = P.x * s0 + cn.x; Q.x = Q.x * s0 + cd.x;
                P.y = P.y * s1 + cn.y; Q.y = Q.y * s1 + cd.y;
                P.z = P.z * s2 + cn.z; Q.z = Q.z * s2 + cd.z;
                P.w = P.w * s3 + cn.w; Q.w = Q.w * s3 + cd.w;
            }
            float r0 = pre.x + P.x / Q.x, r1 = pre.y + P.y / Q.y;
            float r2 = pre.z + P.z / Q.z, r3 = pre.w + P.w / Q.w;
            ms[nl][b4 + 0] = (r0 > 0.f ? r0 : 0.f) + xv0;
            ms[nl][b4 + 1] = (r1 > 0.f ? r1 : 0.f) + xv1;
            ms[nl][b4 + 2] = (r2 > 0.f ? r2 : 0.f) + xv2;
            ms[nl][b4 + 3] = (r3 > 0.f ? r3 : 0.f) + xv3;
        }
        __syncthreads();
        {
            int bl = tid >> 2, no = (tid & 3) * 4;
            float4 v = make_float4(ms[no][bl], ms[no + 1][bl], ms[no + 2][bl], ms[no + 3][bl]);
            *(float4*)(g_mixed + (size_t)bl * NN + n0 + no) = v;
        }
    }
    gsync(&g_ep2, &g_ct2, base, 1, K2_BLOCKS);

    {
        int mt = bid & 7, sp = bid >> 3;
        int kb = sp * 128, ke = kb + 128; if (ke > NN) ke = NN;
        gemm_tile64(w1, g_mixed, g_part2 + (size_t)sp * EMBED * BB, EMBED,
                    mt * 64, kb, ke, dsm, tid);
    }
}

// ============================================================================
// K3: hid (128 blocks) -> barrier -> logits (blocks 0..19).
// ============================================================================
__global__ __launch_bounds__(256)
void k_tail(const float* __restrict__ b1, const float* __restrict__ w2,
            const float* __restrict__ b2, float* __restrict__ out)
{
    const int bid = blockIdx.x, tid = threadIdx.x;
    unsigned base = 0;
    if (tid == 0) base = *(volatile unsigned*)&g_ep3;

    {
        int i = bid * 256 + tid;                   // 8192 float4 over 32768 threads
        if (i < EMBED * BB / 4) {
            int idx4 = i * 4;
            int e = idx4 >> 6;
            float bb1 = b1[e];
            float4 s = make_float4(bb1, bb1, bb1, bb1);
#pragma unroll
            for (int p = 0; p < SPLIT1; p++) {
                float4 v = *(float4*)(g_part2 + (size_t)p * EMBED * BB + idx4);
                s.x += v.x; s.y += v.y; s.z += v.z; s.w += v.w;
            }
            float4 h;
            h.x = 1.f - __fdividef(2.f, __expf(2.f * s.x) + 1.f);
            h.y = 1.f - __fdividef(2.f, __expf(2.f * s.y) + 1.f);
            h.z = 1.f - __fdividef(2.f, __expf(2.f * s.z) + 1.f);
            h.w = 1.f - __fdividef(2.f, __expf(2.f * s.w) + 1.f);
            *(float4*)(g_hT + idx4) = h;
        }
    }
    gsync(&g_ep3, &g_ct3, base, 1, K3_BLOCKS);

    if (bid < LABELS) {
        int l = bid;
        int b = tid & 63, qq = tid >> 6;
        const float* wr = w2 + l * EMBED + qq * 128;
        const float* hp = g_hT + (qq * 128) * BB + b;
        float acc = 0.f;
#pragma unroll 8
        for (int e = 0; e < 128; e++) acc += wr[e] * hp[e * BB];
        __shared__ float s[256];
        s[tid] = acc;
        __syncthreads();
        if (qq == 0)
            out[b * LABELS + l] = s[b] + s[64 + b] + s[128 + b] + s[192 + b] + b2[l];
    }
}

extern "C" void kernel_launch(void* const* d_in, const int* in_sizes, int n_in,
                              void* d_out, int out_size) {
    const float* feature    = (const float*)d_in[0];
    const float* init_graph = (const float*)d_in[1];
    const float* theta_w    = (const float*)d_in[2];
    const float* theta_b    = (const float*)d_in[3];
    const float* phi_w      = (const float*)d_in[4];
    /* phi_b cancels in the softmax */
    const float* fc1_w      = (const float*)d_in[6];
    const float* fc1_b      = (const float*)d_in[7];
    const float* fc2_w      = (const float*)d_in[8];
    const float* fc2_b      = (const float*)d_in[9];
    float* out = (float*)d_out;

    cudaFuncSetAttribute(k_gemm0, cudaFuncAttributeMaxDynamicSharedMemorySize, DSMEM1);
    cudaFuncSetAttribute(k_mid, cudaFuncAttributeMaxDynamicSharedMemorySize, DSMEM2);

    k_gemm0<<<G0_BLOCKS + 64, 512, DSMEM1>>>(init_graph, feature, theta_w, theta_b, phi_w);
    k_mid<<<K2_BLOCKS, 256, DSMEM2>>>(feature, fc1_w);
    k_tail<<<K3_BLOCKS, 256>>>(fc1_b, fc2_w, fc2_b, out);
}

// round 15
// speedup vs baseline: 1.2319x; 1.1060x over previous
#include <cuda_runtime.h>
#include <cuda_bf16.h>
#include <math.h>
#include <stdint.h>

#define NN 2000
#define BB 64
#define EMBED 512
#define LABELS 20
#define NC 31            // Taylor degree 30

// ---- gemm0 (K1): MT=128 tile, 16 mtiles x 9 splits of 224, 512 threads ----
#define SPLIT0 9
#define SPLEN0 224
#define G0_BLOCKS 144
#define A_PAD 72
#define K1_ALO 18432
#define K1_BHI 36864
#define K1_BLO 46080
#define K1_STRIDE 55296
#define DSMEM1 (2 * K1_STRIDE)   // 110592

// ---- gemm1 (K2 phase): MT=64 tile, 256 threads ----
#define TILEB 9216
#define K2_ALO TILEB
#define K2_BHI (2 * TILEB)
#define K2_BLO (3 * TILEB)
#define K2_STRIDE (4 * TILEB)
#define DSMEM2 (2 * K2_STRIDE)   // 73728
#define SPLIT1 16
#define K2_BLOCKS 128
#define K3_BLOCKS 128

// ---- scratch ----
__device__ float g_mixed[BB * NN];           // [b][n]
__device__ float g_part1[SPLIT0 * NN * BB];  // [sp][n][b]
__device__ float g_part2[SPLIT1 * EMBED * BB];
__device__ float g_hT[EMBED * BB];           // [e][b]
__device__ float g_cn[NC][BB];
__device__ float g_cd[NC][BB];
__device__ float g_alpha, g_gamma;
__device__ unsigned g_ep2, g_ct2, g_ep3, g_ct3;   // monotonic barriers

__device__ __forceinline__ void gsync(unsigned* ep, unsigned* ct, unsigned base,
                                      unsigned k, unsigned nblk) {
    __syncthreads();
    if (threadIdx.x == 0) {
        __threadfence();
        unsigned t = atomicAdd(ct, 1u);
        if (t == nblk - 1) {
            *ct = 0;
            __threadfence();
            atomicAdd(ep, 1u);
        } else {
            while (*(volatile unsigned*)ep - base < k) { __nanosleep(64); }
        }
        __threadfence();
    }
    __syncthreads();
}

__device__ __forceinline__ void mma16816(float* d, const uint32_t* a, const uint32_t* b) {
    asm volatile(
        "mma.sync.aligned.m16n8k16.row.col.f32.bf16.bf16.f32 "
        "{%0,%1,%2,%3}, {%4,%5,%6,%7}, {%8,%9}, {%0,%1,%2,%3};\n"
        : "+f"(d[0]), "+f"(d[1]), "+f"(d[2]), "+f"(d[3])
        : "r"(a[0]), "r"(a[1]), "r"(a[2]), "r"(a[3]), "r"(b[0]), "r"(b[1]));
}

__device__ __forceinline__ void ldsm_x4(uint32_t* r, uint32_t addr) {
    asm volatile("ldmatrix.sync.aligned.m8n8.x4.shared.b16 {%0,%1,%2,%3}, [%4];"
        : "=r"(r[0]), "=r"(r[1]), "=r"(r[2]), "=r"(r[3]) : "r"(addr));
}

__device__ __forceinline__ void split_store(char* hi, char* lo, int byte, float4 v) {
    __nv_bfloat16 hx = __float2bfloat16(v.x), hy = __float2bfloat16(v.y);
    __nv_bfloat16 hz = __float2bfloat16(v.z), hw = __float2bfloat16(v.w);
    float lx = v.x - __bfloat162float(hx), ly = v.y - __bfloat162float(hy);
    float lz = v.z - __bfloat162float(hz), lw = v.w - __bfloat162float(hw);
    uint2 h2, l2;
    h2.x = (unsigned)__bfloat16_as_ushort(hx) | ((unsigned)__bfloat16_as_ushort(hy) << 16);
    h2.y = (unsigned)__bfloat16_as_ushort(hz) | ((unsigned)__bfloat16_as_ushort(hw) << 16);
    __nv_bfloat16 ax = __float2bfloat16(lx), ay = __float2bfloat16(ly);
    __nv_bfloat16 az = __float2bfloat16(lz), aw = __float2bfloat16(lw);
    l2.x = (unsigned)__bfloat16_as_ushort(ax) | ((unsigned)__bfloat16_as_ushort(ay) << 16);
    l2.y = (unsigned)__bfloat16_as_ushort(az) | ((unsigned)__bfloat16_as_ushort(aw) << 16);
    *(uint2*)(hi + byte) = h2;
    *(uint2*)(lo + byte) = l2;
}

// ============================================================================
// K1: gemm0, 512 threads, 4x4 warp grid over 128x64 tile, ldmatrix fragments.
//     Moments fold into blocks 0..63 as epilogue. Grid = 144 (one wave).
// ============================================================================
__global__ __launch_bounds__(512, 1)
void k_gemm0(const float* __restrict__ IG, const float* __restrict__ feat,
             const float* __restrict__ tw, const float* __restrict__ tb,
             const float* __restrict__ pw)
{
    extern __shared__ __align__(16) char dsm[];
    const int bid = blockIdx.x, tid = threadIdx.x;
    const int wid = tid >> 5, lane = tid & 31;
    const int mt = bid & 15, sp = bid >> 4;
    const int rb = mt * 128;
    const int kb = sp * SPLEN0;
    int ke = kb + SPLEN0; if (ke > NN) ke = NN;
    const int nc = (ke - kb + 63) >> 6;

    const int warp_m = wid >> 2;          // 0..3 -> rows *32
    const int warp_n = wid & 3;           // 0..3 -> cols *16
    const int g = lane >> 2, tig = lane & 3;

    const int ar = tid >> 2;              // A row 0..127
    const int aq = (tid & 3) * 16;        // A k quarter
    const int brr = tid >> 3;             // B row 0..63
    const int bq = (tid & 7) * 8;         // B k eighth
    const bool rok = (rb + ar) < NN;
    const float* arow = IG + (size_t)(rb + ar) * NN;
    const float* brow = feat + (size_t)brr * NN;

    const uint32_t sbase = (uint32_t)__cvta_generic_to_shared(dsm);
    // ldmatrix lane->address maps (verified R12): x4 = {rows 0-7@k0, 8-15@k0, 0-7@k8, 8-15@k8}
    const int aoff  = (warp_m * 32 + (lane & 15)) * (A_PAD * 2) + (lane >> 4) * 16;
    const int aoff2 = aoff + 16 * (A_PAD * 2);
    const int boff  = (warp_n * 16 + (lane & 15)) * (A_PAD * 2) + (lane >> 4) * 16;

    float acc[2][2][4];
#pragma unroll
    for (int t = 0; t < 2; t++)
#pragma unroll
        for (int u = 0; u < 2; u++)
#pragma unroll
            for (int j = 0; j < 4; j++) acc[t][u][j] = 0.f;

    float4 ra[4], rbv[2];
    auto ldg_chunk = [&](int c) {
        int m0 = kb + c * 64;
        int mlen = ke - m0; if (mlen > 64) mlen = 64;
#pragma unroll
        for (int i = 0; i < 4; i++) {
            int kk = aq + i * 4;
            float4 v = make_float4(0.f, 0.f, 0.f, 0.f);
            if (rok && kk + 4 <= mlen) v = *(const float4*)(arow + m0 + kk);
            ra[i] = v;
        }
#pragma unroll
        for (int i = 0; i < 2; i++) {
            int kk = bq + i * 4;
            float4 v = make_float4(0.f, 0.f, 0.f, 0.f);
            if (kk + 4 <= mlen) v = *(const float4*)(brow + m0 + kk);
            rbv[i] = v;
        }
    };
    auto cvt_store = [&](int p) {
        char* base = dsm + p * K1_STRIDE;
#pragma unroll
        for (int i = 0; i < 4; i++) {
            int kk = aq + i * 4;
            split_store(base, base + K1_ALO, ar * (A_PAD * 2) + kk * 2, ra[i]);
        }
#pragma unroll
        for (int i = 0; i < 2; i++) {
            int kk = bq + i * 4;
            split_store(base + K1_BHI, base + K1_BLO, brr * (A_PAD * 2) + kk * 2, rbv[i]);
        }
    };
    auto compute = [&](int p) {
        uint32_t bA = sbase + p * K1_STRIDE;
#pragma unroll
        for (int ks = 0; ks < 4; ks++) {
            const int kof = ks * 32;   // 16 k * 2B
            uint32_t a0[4], a1[4], l0[4], l1[4], bh4[4], bl4[4];
            ldsm_x4(a0, bA + aoff + kof);
            ldsm_x4(a1, bA + aoff2 + kof);
            ldsm_x4(l0, bA + K1_ALO + aoff + kof);
            ldsm_x4(l1, bA + K1_ALO + aoff2 + kof);
            ldsm_x4(bh4, bA + K1_BHI + boff + kof);
            ldsm_x4(bl4, bA + K1_BLO + boff + kof);
            uint32_t b00[2] = {bh4[0], bh4[2]}, b01[2] = {bh4[1], bh4[3]};
            uint32_t c00[2] = {bl4[0], bl4[2]}, c01[2] = {bl4[1], bl4[3]};
            mma16816(acc[0][0], a0, b00); mma16816(acc[0][0], a0, c00); mma16816(acc[0][0], l0, b00);
            mma16816(acc[0][1], a0, b01); mma16816(acc[0][1], a0, c01); mma16816(acc[0][1], l0, b01);
            mma16816(acc[1][0], a1, b00); mma16816(acc[1][0], a1, c00); mma16816(acc[1][0], l1, b00);
            mma16816(acc[1][1], a1, b01); mma16816(acc[1][1], a1, c01); mma16816(acc[1][1], l1, b01);
        }
    };

    ldg_chunk(0);
    for (int c = 0; c < nc; c++) {
        int p = c & 1;
        cvt_store(p);
        if (c + 1 < nc) ldg_chunk(c + 1);
        __syncthreads();
        compute(p);
    }

    float* dst = g_part1 + (size_t)sp * NN * BB;
#pragma unroll
    for (int t = 0; t < 2; t++) {
        int r0 = rb + warp_m * 32 + t * 16 + g;
#pragma unroll
        for (int u = 0; u < 2; u++) {
            int cn = warp_n * 16 + u * 8 + tig * 2;
            if (r0 < NN)
                *(float2*)(dst + (size_t)r0 * BB + cn) = make_float2(acc[t][u][0], acc[t][u][1]);
            if (r0 + 8 < NN)
                *(float2*)(dst + (size_t)(r0 + 8) * BB + cn) = make_float2(acc[t][u][2], acc[t][u][3]);
        }
    }

    // ----------------- moments epilogue on blocks 0..63 ---------------------
    if (bid < 64) {
        __syncthreads();                    // smem free for reuse
        float* red = (float*)dsm;           // [32][16]
        float* sM = (float*)(dsm + 32 * 16 * 4);
        if (bid == 0) {
            float* sa = sM + 32;            // [64]
            float* sg = sa + 64;            // [64]
            if (tid < 64) { sa[tid] = tw[tid] * pw[tid]; sg[tid] = tb[tid] * pw[tid]; }
            __syncthreads();
            if (tid == 0) {
                float A = 0.f, G = 0.f;
                for (int i = 0; i < 64; i++) { A += sa[i]; G += sg[i]; }
                g_alpha = A; g_gamma = G;
            }
        }
        const int b = bid;
        const float* xr = feat + (size_t)b * NN;
        float acm[32];
#pragma unroll
        for (int k = 0; k < 32; k++) acm[k] = 0.f;
        for (int m = tid; m < NN; m += 512) {
            float v = xr[m];
            float p = 1.f;
#pragma unroll
            for (int k = 0; k < 32; k++) { acm[k] += p; p *= v; }
        }
#pragma unroll
        for (int k = 0; k < 32; k++) {
#pragma unroll
            for (int off = 16; off > 0; off >>= 1)
                acm[k] += __shfl_down_sync(0xffffffffu, acm[k], off);
        }
        if (lane == 0) {
#pragma unroll
            for (int k = 0; k < 32; k++) red[k * 16 + wid] = acm[k];
        }
        __syncthreads();
        if (tid < 32) {
            float s = 0.f;
            for (int w = 0; w < 16; w++) s += red[tid * 16 + w];
            sM[tid] = s;
        }
        __syncthreads();
        if (tid < NC) {
            int k = tid;
            float fact = 1.f;
            for (int i = 2; i <= k; i++) fact *= (float)i;
            g_cd[k][b] = sM[k] / fact;
            g_cn[k][b] = sM[k + 1] / fact;
        }
    }
}

// MT=64 gemm tile for fc1, 256 threads, ldmatrix fragments (verified R12)
__device__ __forceinline__ void gemm_tile64(
    const float* __restrict__ A, const float* __restrict__ Bmat,
    float* __restrict__ dst, int nrows, int rb, int kb, int ke,
    char* dsm, int tid)
{
    const int wid = tid >> 5, lane = tid & 31;
    const int warp_m = wid >> 2, warp_n = wid & 3;
    const int g = lane >> 2, tig = lane & 3;
    const int rr = tid >> 2;
    const int q4 = (tid & 3) * 16;
    const bool rok = (rb + rr) < nrows;
    const float* arow = A + (size_t)(rb + rr) * NN;
    const float* brow = Bmat + (size_t)rr * NN;
    const int nc = (ke - kb + 63) >> 6;

    const uint32_t sbase = (uint32_t)__cvta_generic_to_shared(dsm);
    const int aoff  = (warp_m * 32 + (lane & 15)) * (A_PAD * 2) + (lane >> 4) * 16;
    const int aoff2 = aoff + 16 * (A_PAD * 2);
    const int boff  = (warp_n * 16 + (lane & 15)) * (A_PAD * 2) + (lane >> 4) * 16;

    float acc[2][2][4];
#pragma unroll
    for (int t = 0; t < 2; t++)
#pragma unroll
        for (int u = 0; u < 2; u++)
#pragma unroll
            for (int j = 0; j < 4; j++) acc[t][u][j] = 0.f;

    float4 ra[4], rbv[4];
    auto ldg_chunk = [&](int c) {
        int m0 = kb + c * 64;
        int mlen = ke - m0; if (mlen > 64) mlen = 64;
#pragma unroll
        for (int i = 0; i < 4; i++) {
            int kk = q4 + i * 4;
            bool ok = (kk + 4 <= mlen);
            ra[i] = (rok && ok) ? *(const float4*)(arow + m0 + kk)
                                : make_float4(0.f, 0.f, 0.f, 0.f);
            rbv[i] = ok ? *(const float4*)(brow + m0 + kk)
                        : make_float4(0.f, 0.f, 0.f, 0.f);
        }
    };
    auto cvt_store = [&](int p) {
        char* base = dsm + p * K2_STRIDE;
#pragma unroll
        for (int i = 0; i < 4; i++) {
            int kk = q4 + i * 4;
            split_store(base, base + K2_ALO, rr * (A_PAD * 2) + kk * 2, ra[i]);
            split_store(base + K2_BHI, base + K2_BLO, rr * (A_PAD * 2) + kk * 2, rbv[i]);
        }
    };
    auto compute = [&](int p) {
        uint32_t bA = sbase + p * K2_STRIDE;
#pragma unroll
        for (int ks = 0; ks < 4; ks++) {
            const int kof = ks * 32;
            uint32_t a0[4], a1[4], l0[4], l1[4], bh4[4], bl4[4];
            ldsm_x4(a0, bA + aoff + kof);
            ldsm_x4(a1, bA + aoff2 + kof);
            ldsm_x4(l0, bA + K2_ALO + aoff + kof);
            ldsm_x4(l1, bA + K2_ALO + aoff2 + kof);
            ldsm_x4(bh4, bA + K2_BHI + boff + kof);
            ldsm_x4(bl4, bA + K2_BLO + boff + kof);
            uint32_t b00[2] = {bh4[0], bh4[2]}, b01[2] = {bh4[1], bh4[3]};
            uint32_t c00[2] = {bl4[0], bl4[2]}, c01[2] = {bl4[1], bl4[3]};
            mma16816(acc[0][0], a0, b00); mma16816(acc[0][0], a0, c00); mma16816(acc[0][0], l0, b00);
            mma16816(acc[0][1], a0, b01); mma16816(acc[0][1], a0, c01); mma16816(acc[0][1], l0, b01);
            mma16816(acc[1][0], a1, b00); mma16816(acc[1][0], a1, c00); mma16816(acc[1][0], l1, b00);
            mma16816(acc[1][1], a1, b01); mma16816(acc[1][1], a1, c01); mma16816(acc[1][1], l1, b01);
        }
    };

    ldg_chunk(0);
    for (int c = 0; c < nc; c++) {
        int p = c & 1;
        cvt_store(p);
        if (c + 1 < nc) ldg_chunk(c + 1);
        __syncthreads();
        compute(p);
    }

#pragma unroll
    for (int t = 0; t < 2; t++) {
        int r0 = rb + warp_m * 32 + t * 16 + g;
#pragma unroll
        for (int u = 0; u < 2; u++) {
            int cn = warp_n * 16 + u * 8 + tig * 2;
            if (r0 < nrows)
                *(float2*)(dst + (size_t)r0 * BB + cn) = make_float2(acc[t][u][0], acc[t][u][1]);
            if (r0 + 8 < nrows)
                *(float2*)(dst + (size_t)(r0 + 8) * BB + cn) = make_float2(acc[t][u][2], acc[t][u][3]);
        }
    }
}

// ============================================================================
// K2: mix (125 of 128 blocks) -> barrier -> fc1 gemm (128 blocks).
// ============================================================================
__global__ __launch_bounds__(256, 1)
void k_mid(const float* __restrict__ feat, const float* __restrict__ w1)
{
    extern __shared__ __align__(16) char dsm[];
    const int bid = blockIdx.x, tid = threadIdx.x;
    unsigned base = 0;
    if (tid == 0) base = *(volatile unsigned*)&g_ep2;

    if (bid < 125) {
        __shared__ float xs[64][17];
        __shared__ float ms[16][68];
        const int n0 = bid * 16;
        {
            int bl = tid >> 2, no = (tid & 3) * 4;
            float4 v = *(const float4*)(feat + (size_t)bl * NN + n0 + no);
            xs[bl][no] = v.x; xs[bl][no + 1] = v.y;
            xs[bl][no + 2] = v.z; xs[bl][no + 3] = v.w;
        }
        __syncthreads();
        {
            int nl = tid >> 4, b4 = (tid & 15) * 4;
            size_t row = (size_t)(n0 + nl) * BB + b4;
            float4 pre = *(float4*)(g_part1 + row);
#pragma unroll
            for (int p = 1; p < SPLIT0; p++) {
                float4 v = *(float4*)(g_part1 + (size_t)p * NN * BB + row);
                pre.x += v.x; pre.y += v.y; pre.z += v.z; pre.w += v.w;
            }
            float al = g_alpha, ga = g_gamma;
            float xv0 = xs[b4 + 0][nl], xv1 = xs[b4 + 1][nl];
            float xv2 = xs[b4 + 2][nl], xv3 = xs[b4 + 3][nl];
            float s0 = al * xv0 + ga, s1 = al * xv1 + ga;
            float s2 = al * xv2 + ga, s3 = al * xv3 + ga;
            float4 P = *(float4*)&g_cn[NC - 1][b4];
            float4 Q = *(float4*)&g_cd[NC - 1][b4];
#pragma unroll
            for (int k = NC - 2; k >= 0; k--) {
                float4 cn = *(float4*)&g_cn[k][b4];
                float4 cd = *(float4*)&g_cd[k][b4];
                P.x = P.x * s0 + cn.x; Q.x = Q.x * s0 + cd.x;
                P.y = P.y * s1 + cn.y; Q.y = Q.y * s1 + cd.y;
                P.z = P.z * s2 + cn.z; Q.z = Q.z * s2 + cd.z;
                P.w = P.w * s3 + cn.w; Q.w = Q.w * s3 + cd.w;
            }
            float r0 = pre.x + P.x / Q.x, r1 = pre.y + P.y / Q.y;
            float r2 = pre.z + P.z / Q.z, r3 = pre.w + P.w / Q.w;
            ms[nl][b4 + 0] = (r0 > 0.f ? r0 : 0.f) + xv0;
            ms[nl][b4 + 1] = (r1 > 0.f ? r1 : 0.f) + xv1;
            ms[nl][b4 + 2] = (r2 > 0.f ? r2 : 0.f) + xv2;
            ms[nl][b4 + 3] = (r3 > 0.f ? r3 : 0.f) + xv3;
        }
        __syncthreads();
        {
            int bl = tid >> 2, no = (tid & 3) * 4;
            float4 v = make_float4(ms[no][bl], ms[no + 1][bl], ms[no + 2][bl], ms[no + 3][bl]);
            *(float4*)(g_mixed + (size_t)bl * NN + n0 + no) = v;
        }
    }
    gsync(&g_ep2, &g_ct2, base, 1, K2_BLOCKS);

    {
        int mt = bid & 7, sp = bid >> 3;
        int kb = sp * 128, ke = kb + 128; if (ke > NN) ke = NN;
        gemm_tile64(w1, g_mixed, g_part2 + (size_t)sp * EMBED * BB, EMBED,
                    mt * 64, kb, ke, dsm, tid);
    }
}

// ============================================================================
// K3: hid (128 blocks) -> barrier -> logits (blocks 0..19).
// ============================================================================
__global__ __launch_bounds__(256)
void k_tail(const float* __restrict__ b1, const float* __restrict__ w2,
            const float* __restrict__ b2, float* __restrict__ out)
{
    const int bid = blockIdx.x, tid = threadIdx.x;
    unsigned base = 0;
    if (tid == 0) base = *(volatile unsigned*)&g_ep3;

    {
        int i = bid * 256 + tid;                   // 8192 float4 over 32768 threads
        if (i < EMBED * BB / 4) {
            int idx4 = i * 4;
            int e = idx4 >> 6;
            float bb1 = b1[e];
            float4 s = make_float4(bb1, bb1, bb1, bb1);
#pragma unroll
            for (int p = 0; p < SPLIT1; p++) {
                float4 v = *(float4*)(g_part2 + (size_t)p * EMBED * BB + idx4);
                s.x += v.x; s.y += v.y; s.z += v.z; s.w += v.w;
            }
            float4 h;
            h.x = 1.f - __fdividef(2.f, __expf(2.f * s.x) + 1.f);
            h.y = 1.f - __fdividef(2.f, __expf(2.f * s.y) + 1.f);
            h.z = 1.f - __fdividef(2.f, __expf(2.f * s.z) + 1.f);
            h.w = 1.f - __fdividef(2.f, __expf(2.f * s.w) + 1.f);
            *(float4*)(g_hT + idx4) = h;
        }
    }
    gsync(&g_ep3, &g_ct3, base, 1, K3_BLOCKS);

    if (bid < LABELS) {
        int l = bid;
        int b = tid & 63, qq = tid >> 6;
        const float* wr = w2 + l * EMBED + qq * 128;
        const float* hp = g_hT + (qq * 128) * BB + b;
        float acc = 0.f;
#pragma unroll 8
        for (int e = 0; e < 128; e++) acc += wr[e] * hp[e * BB];
        __shared__ float s[256];
        s[tid] = acc;
        __syncthreads();
        if (qq == 0)
            out[b * LABELS + l] = s[b] + s[64 + b] + s[128 + b] + s[192 + b] + b2[l];
    }
}

extern "C" void kernel_launch(void* const* d_in, const int* in_sizes, int n_in,
                              void* d_out, int out_size) {
    const float* feature    = (const float*)d_in[0];
    const float* init_graph = (const float*)d_in[1];
    const float* theta_w    = (const float*)d_in[2];
    const float* theta_b    = (const float*)d_in[3];
    const float* phi_w      = (const float*)d_in[4];
    /* phi_b cancels in the softmax */
    const float* fc1_w      = (const float*)d_in[6];
    const float* fc1_b      = (const float*)d_in[7];
    const float* fc2_w      = (const float*)d_in[8];
    const float* fc2_b      = (const float*)d_in[9];
    float* out = (float*)d_out;

    cudaFuncSetAttribute(k_gemm0, cudaFuncAttributeMaxDynamicSharedMemorySize, DSMEM1);
    cudaFuncSetAttribute(k_mid, cudaFuncAttributeMaxDynamicSharedMemorySize, DSMEM2);

    k_gemm0<<<G0_BLOCKS, 512, DSMEM1>>>(init_graph, feature, theta_w, theta_b, phi_w);
    k_mid<<<K2_BLOCKS, 256, DSMEM2>>>(feature, fc1_w);
    k_tail<<<K3_BLOCKS, 256>>>(fc1_b, fc2_w, fc2_b, out);
}

// round 16
// speedup vs baseline: 1.3077x; 1.0615x over previous
#include <cuda_runtime.h>
#include <cuda_bf16.h>
#include <math.h>
#include <stdint.h>

#define NN 2000
#define BB 64
#define EMBED 512
#define LABELS 20
#define NC 31            // Taylor degree 30

// ---- gemm0 (K1): MT=128 tile, 16 mtiles x 9 splits of 224, 512 threads ----
#define SPLIT0 9
#define SPLEN0 224
#define G0_BLOCKS 144
#define A_PAD 72
#define K1_ALO 18432
#define K1_BHI 36864
#define K1_BLO 46080
#define K1_STRIDE 55296
#define DSMEM1 (2 * K1_STRIDE)   // 110592

// ---- gemm1 (K2 phase): MT=64 tile, 256 threads ----
#define TILEB 9216
#define K2_ALO TILEB
#define K2_BHI (2 * TILEB)
#define K2_BLO (3 * TILEB)
#define K2_STRIDE (4 * TILEB)
#define DSMEM2 (2 * K2_STRIDE)   // 73728
#define SPLIT1 16
#define K2_BLOCKS 128

// ---- scratch ----
__device__ float g_mixed[BB * NN];           // [b][n]
__device__ float g_part1[SPLIT0 * NN * BB];  // [sp][n][b]
__device__ float g_part2[SPLIT1 * EMBED * BB];
__device__ float g_hT[EMBED * BB];           // [e][b]
__device__ float g_cn[NC][BB];
__device__ float g_cd[NC][BB];
__device__ float g_alpha, g_gamma;
__device__ unsigned g_ep2, g_ct2;            // monotonic barrier (K2)

__device__ __forceinline__ void gsync(unsigned* ep, unsigned* ct, unsigned base,
                                      unsigned k, unsigned nblk) {
    __syncthreads();
    if (threadIdx.x == 0) {
        __threadfence();
        unsigned t = atomicAdd(ct, 1u);
        if (t == nblk - 1) {
            *ct = 0;
            __threadfence();
            atomicAdd(ep, 1u);
        } else {
            while (*(volatile unsigned*)ep - base < k) { __nanosleep(64); }
        }
        __threadfence();
    }
    __syncthreads();
}

__device__ __forceinline__ void mma16816(float* d, const uint32_t* a, const uint32_t* b) {
    asm volatile(
        "mma.sync.aligned.m16n8k16.row.col.f32.bf16.bf16.f32 "
        "{%0,%1,%2,%3}, {%4,%5,%6,%7}, {%8,%9}, {%0,%1,%2,%3};\n"
        : "+f"(d[0]), "+f"(d[1]), "+f"(d[2]), "+f"(d[3])
        : "r"(a[0]), "r"(a[1]), "r"(a[2]), "r"(a[3]), "r"(b[0]), "r"(b[1]));
}

__device__ __forceinline__ void ldsm_x4(uint32_t* r, uint32_t addr) {
    asm volatile("ldmatrix.sync.aligned.m8n8.x4.shared.b16 {%0,%1,%2,%3}, [%4];"
        : "=r"(r[0]), "=r"(r[1]), "=r"(r[2]), "=r"(r[3]) : "r"(addr));
}

// packed split: cvt.rn.bf16x2.f32 converts 2 floats per instruction.
// layout: packed word = bf16(x) in low half, bf16(y) in high half (same as before).
__device__ __forceinline__ void split_store(char* hi, char* lo, int byte, float4 v) {
    uint32_t h01, h23;
    asm("cvt.rn.bf16x2.f32 %0, %1, %2;" : "=r"(h01) : "f"(v.y), "f"(v.x));
    asm("cvt.rn.bf16x2.f32 %0, %1, %2;" : "=r"(h23) : "f"(v.w), "f"(v.z));
    float hx = __uint_as_float(h01 << 16);
    float hy = __uint_as_float(h01 & 0xFFFF0000u);
    float hz = __uint_as_float(h23 << 16);
    float hw = __uint_as_float(h23 & 0xFFFF0000u);
    uint32_t l01, l23;
    asm("cvt.rn.bf16x2.f32 %0, %1, %2;" : "=r"(l01) : "f"(v.y - hy), "f"(v.x - hx));
    asm("cvt.rn.bf16x2.f32 %0, %1, %2;" : "=r"(l23) : "f"(v.w - hw), "f"(v.z - hz));
    *(uint2*)(hi + byte) = make_uint2(h01, h23);
    *(uint2*)(lo + byte) = make_uint2(l01, l23);
}

// ============================================================================
// K1: gemm0, 512 threads, 4x4 warp grid over 128x64 tile, ldmatrix fragments.
//     Moments fold into blocks 0..63 as epilogue. Grid = 144 (one wave).
// ============================================================================
__global__ __launch_bounds__(512, 1)
void k_gemm0(const float* __restrict__ IG, const float* __restrict__ feat,
             const float* __restrict__ tw, const float* __restrict__ tb,
             const float* __restrict__ pw)
{
    extern __shared__ __align__(16) char dsm[];
    const int bid = blockIdx.x, tid = threadIdx.x;
    const int wid = tid >> 5, lane = tid & 31;
    const int mt = bid & 15, sp = bid >> 4;
    const int rb = mt * 128;
    const int kb = sp * SPLEN0;
    int ke = kb + SPLEN0; if (ke > NN) ke = NN;
    const int nc = (ke - kb + 63) >> 6;

    const int warp_m = wid >> 2;
    const int warp_n = wid & 3;
    const int g = lane >> 2, tig = lane & 3;

    const int ar = tid >> 2;
    const int aq = (tid & 3) * 16;
    const int brr = tid >> 3;
    const int bq = (tid & 7) * 8;
    const bool rok = (rb + ar) < NN;
    const float* arow = IG + (size_t)(rb + ar) * NN;
    const float* brow = feat + (size_t)brr * NN;

    const uint32_t sbase = (uint32_t)__cvta_generic_to_shared(dsm);
    const int aoff  = (warp_m * 32 + (lane & 15)) * (A_PAD * 2) + (lane >> 4) * 16;
    const int aoff2 = aoff + 16 * (A_PAD * 2);
    const int boff  = (warp_n * 16 + (lane & 15)) * (A_PAD * 2) + (lane >> 4) * 16;

    float acc[2][2][4];
#pragma unroll
    for (int t = 0; t < 2; t++)
#pragma unroll
        for (int u = 0; u < 2; u++)
#pragma unroll
            for (int j = 0; j < 4; j++) acc[t][u][j] = 0.f;

    float4 ra[4], rbv[2];
    auto ldg_chunk = [&](int c) {
        int m0 = kb + c * 64;
        int mlen = ke - m0; if (mlen > 64) mlen = 64;
#pragma unroll
        for (int i = 0; i < 4; i++) {
            int kk = aq + i * 4;
            float4 v = make_float4(0.f, 0.f, 0.f, 0.f);
            if (rok && kk + 4 <= mlen) v = *(const float4*)(arow + m0 + kk);
            ra[i] = v;
        }
#pragma unroll
        for (int i = 0; i < 2; i++) {
            int kk = bq + i * 4;
            float4 v = make_float4(0.f, 0.f, 0.f, 0.f);
            if (kk + 4 <= mlen) v = *(const float4*)(brow + m0 + kk);
            rbv[i] = v;
        }
    };
    auto cvt_store = [&](int p) {
        char* base = dsm + p * K1_STRIDE;
#pragma unroll
        for (int i = 0; i < 4; i++) {
            int kk = aq + i * 4;
            split_store(base, base + K1_ALO, ar * (A_PAD * 2) + kk * 2, ra[i]);
        }
#pragma unroll
        for (int i = 0; i < 2; i++) {
            int kk = bq + i * 4;
            split_store(base + K1_BHI, base + K1_BLO, brr * (A_PAD * 2) + kk * 2, rbv[i]);
        }
    };
    auto compute = [&](int p) {
        uint32_t bA = sbase + p * K1_STRIDE;
#pragma unroll
        for (int ks = 0; ks < 4; ks++) {
            const int kof = ks * 32;
            uint32_t a0[4], a1[4], l0[4], l1[4], bh4[4], bl4[4];
            ldsm_x4(a0, bA + aoff + kof);
            ldsm_x4(a1, bA + aoff2 + kof);
            ldsm_x4(l0, bA + K1_ALO + aoff + kof);
            ldsm_x4(l1, bA + K1_ALO + aoff2 + kof);
            ldsm_x4(bh4, bA + K1_BHI + boff + kof);
            ldsm_x4(bl4, bA + K1_BLO + boff + kof);
            uint32_t b00[2] = {bh4[0], bh4[2]}, b01[2] = {bh4[1], bh4[3]};
            uint32_t c00[2] = {bl4[0], bl4[2]}, c01[2] = {bl4[1], bl4[3]};
            mma16816(acc[0][0], a0, b00); mma16816(acc[0][0], a0, c00); mma16816(acc[0][0], l0, b00);
            mma16816(acc[0][1], a0, b01); mma16816(acc[0][1], a0, c01); mma16816(acc[0][1], l0, b01);
            mma16816(acc[1][0], a1, b00); mma16816(acc[1][0], a1, c00); mma16816(acc[1][0], l1, b00);
            mma16816(acc[1][1], a1, b01); mma16816(acc[1][1], a1, c01); mma16816(acc[1][1], l1, b01);
        }
    };

    ldg_chunk(0);
    for (int c = 0; c < nc; c++) {
        int p = c & 1;
        cvt_store(p);
        if (c + 1 < nc) ldg_chunk(c + 1);
        __syncthreads();
        compute(p);
    }

    float* dst = g_part1 + (size_t)sp * NN * BB;
#pragma unroll
    for (int t = 0; t < 2; t++) {
        int r0 = rb + warp_m * 32 + t * 16 + g;
#pragma unroll
        for (int u = 0; u < 2; u++) {
            int cn = warp_n * 16 + u * 8 + tig * 2;
            if (r0 < NN)
                *(float2*)(dst + (size_t)r0 * BB + cn) = make_float2(acc[t][u][0], acc[t][u][1]);
            if (r0 + 8 < NN)
                *(float2*)(dst + (size_t)(r0 + 8) * BB + cn) = make_float2(acc[t][u][2], acc[t][u][3]);
        }
    }

    // ----------------- moments epilogue on blocks 0..63 ---------------------
    if (bid < 64) {
        __syncthreads();
        float* red = (float*)dsm;           // [32][16]
        float* sM = (float*)(dsm + 32 * 16 * 4);
        if (bid == 0) {
            float* sa = sM + 32;
            float* sg = sa + 64;
            if (tid < 64) { sa[tid] = tw[tid] * pw[tid]; sg[tid] = tb[tid] * pw[tid]; }
            __syncthreads();
            if (tid == 0) {
                float A = 0.f, G = 0.f;
                for (int i = 0; i < 64; i++) { A += sa[i]; G += sg[i]; }
                g_alpha = A; g_gamma = G;
            }
        }
        const int b = bid;
        const float* xr = feat + (size_t)b * NN;
        float acm[32];
#pragma unroll
        for (int k = 0; k < 32; k++) acm[k] = 0.f;
        for (int m = tid; m < NN; m += 512) {
            float v = xr[m];
            float p = 1.f;
#pragma unroll
            for (int k = 0; k < 32; k++) { acm[k] += p; p *= v; }
        }
#pragma unroll
        for (int k = 0; k < 32; k++) {
#pragma unroll
            for (int off = 16; off > 0; off >>= 1)
                acm[k] += __shfl_down_sync(0xffffffffu, acm[k], off);
        }
        if (lane == 0) {
#pragma unroll
            for (int k = 0; k < 32; k++) red[k * 16 + wid] = acm[k];
        }
        __syncthreads();
        if (tid < 32) {
            float s = 0.f;
            for (int w = 0; w < 16; w++) s += red[tid * 16 + w];
            sM[tid] = s;
        }
        __syncthreads();
        if (tid < NC) {
            int k = tid;
            float fact = 1.f;
            for (int i = 2; i <= k; i++) fact *= (float)i;
            g_cd[k][b] = sM[k] / fact;
            g_cn[k][b] = sM[k + 1] / fact;
        }
    }
}

// MT=64 gemm tile for fc1, 256 threads, ldmatrix fragments
__device__ __forceinline__ void gemm_tile64(
    const float* __restrict__ A, const float* __restrict__ Bmat,
    float* __restrict__ dst, int nrows, int rb, int kb, int ke,
    char* dsm, int tid)
{
    const int wid = tid >> 5, lane = tid & 31;
    const int warp_m = wid >> 2, warp_n = wid & 3;
    const int g = lane >> 2, tig = lane & 3;
    const int rr = tid >> 2;
    const int q4 = (tid & 3) * 16;
    const bool rok = (rb + rr) < nrows;
    const float* arow = A + (size_t)(rb + rr) * NN;
    const float* brow = Bmat + (size_t)rr * NN;
    const int nc = (ke - kb + 63) >> 6;

    const uint32_t sbase = (uint32_t)__cvta_generic_to_shared(dsm);
    const int aoff  = (warp_m * 32 + (lane & 15)) * (A_PAD * 2) + (lane >> 4) * 16;
    const int aoff2 = aoff + 16 * (A_PAD * 2);
    const int boff  = (warp_n * 16 + (lane & 15)) * (A_PAD * 2) + (lane >> 4) * 16;

    float acc[2][2][4];
#pragma unroll
    for (int t = 0; t < 2; t++)
#pragma unroll
        for (int u = 0; u < 2; u++)
#pragma unroll
            for (int j = 0; j < 4; j++) acc[t][u][j] = 0.f;

    float4 ra[4], rbv[4];
    auto ldg_chunk = [&](int c) {
        int m0 = kb + c * 64;
        int mlen = ke - m0; if (mlen > 64) mlen = 64;
#pragma unroll
        for (int i = 0; i < 4; i++) {
            int kk = q4 + i * 4;
            bool ok = (kk + 4 <= mlen);
            ra[i] = (rok && ok) ? *(const float4*)(arow + m0 + kk)
                                : make_float4(0.f, 0.f, 0.f, 0.f);
            rbv[i] = ok ? *(const float4*)(brow + m0 + kk)
                        : make_float4(0.f, 0.f, 0.f, 0.f);
        }
    };
    auto cvt_store = [&](int p) {
        char* base = dsm + p * K2_STRIDE;
#pragma unroll
        for (int i = 0; i < 4; i++) {
            int kk = q4 + i * 4;
            split_store(base, base + K2_ALO, rr * (A_PAD * 2) + kk * 2, ra[i]);
            split_store(base + K2_BHI, base + K2_BLO, rr * (A_PAD * 2) + kk * 2, rbv[i]);
        }
    };
    auto compute = [&](int p) {
        uint32_t bA = sbase + p * K2_STRIDE;
#pragma unroll
        for (int ks = 0; ks < 4; ks++) {
            const int kof = ks * 32;
            uint32_t a0[4], a1[4], l0[4], l1[4], bh4[4], bl4[4];
            ldsm_x4(a0, bA + aoff + kof);
            ldsm_x4(a1, bA + aoff2 + kof);
            ldsm_x4(l0, bA + K2_ALO + aoff + kof);
            ldsm_x4(l1, bA + K2_ALO + aoff2 + kof);
            ldsm_x4(bh4, bA + K2_BHI + boff + kof);
            ldsm_x4(bl4, bA + K2_BLO + boff + kof);
            uint32_t b00[2] = {bh4[0], bh4[2]}, b01[2] = {bh4[1], bh4[3]};
            uint32_t c00[2] = {bl4[0], bl4[2]}, c01[2] = {bl4[1], bl4[3]};
            mma16816(acc[0][0], a0, b00); mma16816(acc[0][0], a0, c00); mma16816(acc[0][0], l0, b00);
            mma16816(acc[0][1], a0, b01); mma16816(acc[0][1], a0, c01); mma16816(acc[0][1], l0, b01);
            mma16816(acc[1][0], a1, b00); mma16816(acc[1][0], a1, c00); mma16816(acc[1][0], l1, b00);
            mma16816(acc[1][1], a1, b01); mma16816(acc[1][1], a1, c01); mma16816(acc[1][1], l1, b01);
        }
    };

    ldg_chunk(0);
    for (int c = 0; c < nc; c++) {
        int p = c & 1;
        cvt_store(p);
        if (c + 1 < nc) ldg_chunk(c + 1);
        __syncthreads();
        compute(p);
    }

#pragma unroll
    for (int t = 0; t < 2; t++) {
        int r0 = rb + warp_m * 32 + t * 16 + g;
#pragma unroll
        for (int u = 0; u < 2; u++) {
            int cn = warp_n * 16 + u * 8 + tig * 2;
            if (r0 < nrows)
                *(float2*)(dst + (size_t)r0 * BB + cn) = make_float2(acc[t][u][0], acc[t][u][1]);
            if (r0 + 8 < nrows)
                *(float2*)(dst + (size_t)(r0 + 8) * BB + cn) = make_float2(acc[t][u][2], acc[t][u][3]);
        }
    }
    __syncthreads();   // smem safe for later phases
}

// ============================================================================
// K2: mix -> gsync -> fc1 gemm -> gsync -> hid -> gsync -> logits.
//     128 blocks, 256 threads (all co-resident).
// ============================================================================
__global__ __launch_bounds__(256, 1)
void k_mid(const float* __restrict__ feat, const float* __restrict__ w1,
           const float* __restrict__ b1, const float* __restrict__ w2,
           const float* __restrict__ b2, float* __restrict__ out)
{
    extern __shared__ __align__(16) char dsm[];
    const int bid = blockIdx.x, tid = threadIdx.x;
    unsigned base = 0;
    if (tid == 0) base = *(volatile unsigned*)&g_ep2;

    // ---------------- phase 0: mix (blocks 0..124) --------------------------
    if (bid < 125) {
        float (*xs)[17] = (float(*)[17])dsm;                 // [64][17]
        float (*ms)[68] = (float(*)[68])(dsm + 64 * 17 * 4); // [16][68]
        const int n0 = bid * 16;
        {
            int bl = tid >> 2, no = (tid & 3) * 4;
            float4 v = *(const float4*)(feat + (size_t)bl * NN + n0 + no);
            xs[bl][no] = v.x; xs[bl][no + 1] = v.y;
            xs[bl][no + 2] = v.z; xs[bl][no + 3] = v.w;
        }
        __syncthreads();
        {
            int nl = tid >> 4, b4 = (tid & 15) * 4;
            size_t row = (size_t)(n0 + nl) * BB + b4;
            float4 pre = *(float4*)(g_part1 + row);
#pragma unroll
            for (int p = 1; p < SPLIT0; p++) {
                float4 v = *(float4*)(g_part1 + (size_t)p * NN * BB + row);
                pre.x += v.x; pre.y += v.y; pre.z += v.z; pre.w += v.w;
            }
            float al = g_alpha, ga = g_gamma;
            float xv0 = xs[b4 + 0][nl], xv1 = xs[b4 + 1][nl];
            float xv2 = xs[b4 + 2][nl], xv3 = xs[b4 + 3][nl];
            float s0 = al * xv0 + ga, s1 = al * xv1 + ga;
            float s2 = al * xv2 + ga, s3 = al * xv3 + ga;
            float4 P = *(float4*)&g_cn[NC - 1][b4];
            float4 Q = *(float4*)&g_cd[NC - 1][b4];
#pragma unroll
            for (int k = NC - 2; k >= 0; k--) {
                float4 cn = *(float4*)&g_cn[k][b4];
                float4 cd = *(float4*)&g_cd[k][b4];
                P.x = P.x * s0 + cn.x; Q.x = Q.x * s0 + cd.x;
                P.y = P.y * s1 + cn.y; Q.y = Q.y * s1 + cd.y;
                P.z = P.z * s2 + cn.z; Q.z = Q.z * s2 + cd.z;
                P.w = P.w * s3 + cn.w; Q.w = Q.w * s3 + cd.w;
            }
            float r0 = pre.x + P.x / Q.x, r1 = pre.y + P.y / Q.y;
            float r2 = pre.z + P.z / Q.z, r3 = pre.w + P.w / Q.w;
            ms[nl][b4 + 0] = (r0 > 0.f ? r0 : 0.f) + xv0;
            ms[nl][b4 + 1] = (r1 > 0.f ? r1 : 0.f) + xv1;
            ms[nl][b4 + 2] = (r2 > 0.f ? r2 : 0.f) + xv2;
            ms[nl][b4 + 3] = (r3 > 0.f ? r3 : 0.f) + xv3;
        }
        __syncthreads();
        {
            int bl = tid >> 2, no = (tid & 3) * 4;
            float4 v = make_float4(ms[no][bl], ms[no + 1][bl], ms[no + 2][bl], ms[no + 3][bl]);
            *(float4*)(g_mixed + (size_t)bl * NN + n0 + no) = v;
        }
        __syncthreads();
    }
    gsync(&g_ep2, &g_ct2, base, 1, K2_BLOCKS);

    // ---------------- phase 1: fc1 gemm --------------------------------------
    {
        int mt = bid & 7, sp = bid >> 3;
        int kb = sp * 128, ke = kb + 128; if (ke > NN) ke = NN;
        gemm_tile64(w1, g_mixed, g_part2 + (size_t)sp * EMBED * BB, EMBED,
                    mt * 64, kb, ke, dsm, tid);
    }
    gsync(&g_ep2, &g_ct2, base, 2, K2_BLOCKS);

    // ---------------- phase 2: hid (reduce + bias + fast tanh) ---------------
    {
        int i = bid * 256 + tid;               // 8192 float4 over 32768 threads
        if (i < EMBED * BB / 4) {
            int idx4 = i * 4;
            int e = idx4 >> 6;
            float bb1 = b1[e];
            float4 s = make_float4(bb1, bb1, bb1, bb1);
#pragma unroll
            for (int p = 0; p < SPLIT1; p++) {
                float4 v = *(float4*)(g_part2 + (size_t)p * EMBED * BB + idx4);
                s.x += v.x; s.y += v.y; s.z += v.z; s.w += v.w;
            }
            float4 h;
            h.x = 1.f - __fdividef(2.f, __expf(2.f * s.x) + 1.f);
            h.y = 1.f - __fdividef(2.f, __expf(2.f * s.y) + 1.f);
            h.z = 1.f - __fdividef(2.f, __expf(2.f * s.z) + 1.f);
            h.w = 1.f - __fdividef(2.f, __expf(2.f * s.w) + 1.f);
            *(float4*)(g_hT + idx4) = h;
        }
    }
    gsync(&g_ep2, &g_ct2, base, 3, K2_BLOCKS);

    // ---------------- phase 3: logits (blocks 0..19) -------------------------
    if (bid < LABELS) {
        int l = bid;
        int b = tid & 63, qq = tid >> 6;
        const float* wr = w2 + l * EMBED + qq * 128;
        const float* hp = g_hT + (qq * 128) * BB + b;
        float acc = 0.f;
#pragma unroll 8
        for (int e = 0; e < 128; e++) acc += wr[e] * hp[e * BB];
        float* s = (float*)dsm;
        s[tid] = acc;
        __syncthreads();
        if (qq == 0)
            out[b * LABELS + l] = s[b] + s[64 + b] + s[128 + b] + s[192 + b] + b2[l];
    }
}

extern "C" void kernel_launch(void* const* d_in, const int* in_sizes, int n_in,
                              void* d_out, int out_size) {
    const float* feature    = (const float*)d_in[0];
    const float* init_graph = (const float*)d_in[1];
    const float* theta_w    = (const float*)d_in[2];
    const float* theta_b    = (const float*)d_in[3];
    const float* phi_w      = (const float*)d_in[4];
    /* phi_b cancels in the softmax */
    const float* fc1_w      = (const float*)d_in[6];
    const float* fc1_b      = (const float*)d_in[7];
    const float* fc2_w      = (const float*)d_in[8];
    const float* fc2_b      = (const float*)d_in[9];
    float* out = (float*)d_out;

    cudaFuncSetAttribute(k_gemm0, cudaFuncAttributeMaxDynamicSharedMemorySize, DSMEM1);
    cudaFuncSetAttribute(k_mid, cudaFuncAttributeMaxDynamicSharedMemorySize, DSMEM2);

    k_gemm0<<<G0_BLOCKS, 512, DSMEM1>>>(init_graph, feature, theta_w, theta_b, phi_w);
    k_mid<<<K2_BLOCKS, 256, DSMEM2>>>(feature, fc1_w, fc1_b, fc2_w, fc2_b, out);
}